// round 9
// baseline (speedup 1.0000x reference)
#include <cuda_runtime.h>
#include <cuda_fp16.h>
#include <cuda_fp8.h>
#include <cstdint>

// Fused gate_up GEMM + SiLU*mul + per-128-group fp8-e4m3 quant via mma.sync
// (HMMA m16n8k16 fp16/fp32-acc). fp16 2-way split, W pre-scaled x64:
// gate_up*64 = x0w0 + x1w0 + x0w1 (dropped x1w1 ~2^-22). Epilogue descales.
//
// R9 = R5's winning tile (CTA 64x256, warp 32x64, 256 thr) + 4-stage K=32
// cp.async ring with a single __syncthreads per stage + distance-4 MMA order.
//
// Output layout (float32): [T*I fp8-rounded values] ++ [T*(I/128) scales]

#define T_DIM 4096
#define H_DIM 4096
#define I_DIM 14336
#define NGROUPS (I_DIM / 128)

static const size_t XS_PLANE = (size_t)T_DIM * H_DIM;
static const size_t WS_PLANE = (size_t)2 * I_DIM * H_DIM;

__device__ __align__(16) __half g_xs[2ull * 4096ull * 4096ull];   //  64 MB
__device__ __align__(16) __half g_ws[2ull * 28672ull * 4096ull];  // 448 MB

// ---------------------------------------------------------------- pre-pass
__global__ __launch_bounds__(256)
void split_x_kernel(const float* __restrict__ src)
{
    const size_t n4 = XS_PLANE / 4;
    size_t i = (size_t)blockIdx.x * blockDim.x + threadIdx.x;
    const size_t stride = (size_t)gridDim.x * blockDim.x;
    for (; i < n4; i += stride) {
        float4 v = ((const float4*)src)[i];
        float f[4] = {v.x, v.y, v.z, v.w};
        __half h0[4], h1[4];
#pragma unroll
        for (int e = 0; e < 4; ++e) {
            h0[e] = __float2half_rn(f[e]);
            h1[e] = __float2half_rn(f[e] - __half2float(h0[e]));
        }
        ((__half2*)(g_xs))[i * 2]                = __halves2half2(h0[0], h0[1]);
        ((__half2*)(g_xs))[i * 2 + 1]            = __halves2half2(h0[2], h0[3]);
        ((__half2*)(g_xs + XS_PLANE))[i * 2]     = __halves2half2(h1[0], h1[1]);
        ((__half2*)(g_xs + XS_PLANE))[i * 2 + 1] = __halves2half2(h1[2], h1[3]);
    }
}

__global__ __launch_bounds__(256)
void split_w_kernel(const float* __restrict__ src)
{
    const size_t n4 = WS_PLANE / 4;
    size_t i = (size_t)blockIdx.x * blockDim.x + threadIdx.x;
    const size_t stride = (size_t)gridDim.x * blockDim.x;
    for (; i < n4; i += stride) {
        float4 v = ((const float4*)src)[i];
        float f[4] = {v.x * 64.0f, v.y * 64.0f, v.z * 64.0f, v.w * 64.0f};
        __half h0[4], h1[4];
#pragma unroll
        for (int e = 0; e < 4; ++e) {
            h0[e] = __float2half_rn(f[e]);
            h1[e] = __float2half_rn(f[e] - __half2float(h0[e]));
        }
        ((__half2*)(g_ws))[i * 2]                = __halves2half2(h0[0], h0[1]);
        ((__half2*)(g_ws))[i * 2 + 1]            = __halves2half2(h0[2], h0[3]);
        ((__half2*)(g_ws + WS_PLANE))[i * 2]     = __halves2half2(h1[0], h1[1]);
        ((__half2*)(g_ws + WS_PLANE))[i * 2 + 1] = __halves2half2(h1[2], h1[3]);
    }
}

// ---------------------------------------------------------------- main GEMM
// Stage (K=32): A0|A1 (64x64B = 4KB each) + B0|B1 (256x64B = 16KB each).
#define STG      40960
#define A1_OFF   4096
#define B_OFF    8192
#define BP_OFF   16384                // B1 = B_OFF + BP_OFF
#define SMEM_SZ  (4 * STG)            // 160 KB
#define YS       264

__device__ __forceinline__ uint32_t s2u(const void* p) {
    uint32_t a;
    asm("{ .reg .u64 t; cvta.to.shared.u64 t, %1; cvt.u32.u64 %0, t; }"
        : "=r"(a) : "l"(p));
    return a;
}
__device__ __forceinline__ void cp16(uint32_t s, const void* g) {
    asm volatile("cp.async.cg.shared.global [%0], [%1], 16;"
                 :: "r"(s), "l"(g) : "memory");
}
#define CP_COMMIT() asm volatile("cp.async.commit_group;" ::: "memory")
#define CP_WAIT2()  asm volatile("cp.async.wait_group 2;" ::: "memory")
#define CP_WAIT0()  asm volatile("cp.async.wait_group 0;" ::: "memory")

__device__ __forceinline__ void ldsm4(uint32_t* r, uint32_t addr) {
    asm volatile("ldmatrix.sync.aligned.m8n8.x4.shared.b16 {%0,%1,%2,%3}, [%4];"
                 : "=r"(r[0]), "=r"(r[1]), "=r"(r[2]), "=r"(r[3]) : "r"(addr));
}
__device__ __forceinline__ void mma16816(float* c, const uint32_t* a,
                                         uint32_t b0, uint32_t b1) {
    asm volatile(
        "mma.sync.aligned.m16n8k16.row.col.f32.f16.f16.f32 "
        "{%0,%1,%2,%3}, {%4,%5,%6,%7}, {%8,%9}, {%0,%1,%2,%3};"
        : "+f"(c[0]), "+f"(c[1]), "+f"(c[2]), "+f"(c[3])
        : "r"(a[0]), "r"(a[1]), "r"(a[2]), "r"(a[3]), "r"(b0), "r"(b1));
}

__global__ __launch_bounds__(256, 1)
void mlp_mma_kernel(float* __restrict__ out)
{
    extern __shared__ __align__(1024) char smem[];
    const uint32_t sb = s2u(smem);
    const int tid = threadIdx.x;
    const int lane = tid & 31, wid = tid >> 5;
    const int wm = wid >> 2, wn = wid & 3;       // 2x4 warp grid
    const int row0 = blockIdx.x * 64;
    const int g0   = blockIdx.y * 128;

    // ---- producer: 10 x 16B chunks per thread per stage ----
    const int kc    = tid & 3;                   // 16B chunk within 64B row
    const int rowid = tid >> 2;                  // 0..63
    const uint32_t swx = (uint32_t)((kc * 16) ^ ((rowid & 6) << 3));

    const __half* gA = g_xs + (size_t)(row0 + rowid) * H_DIM + kc * 8;
    const uint32_t offA = (uint32_t)(rowid * 64) + swx;

    const __half* gB[4];
    uint32_t offB[4];
#pragma unroll
    for (int j = 0; j < 4; ++j) {
        int n = rowid + 64 * j;                  // 0..255
        size_t wr = (n < 128) ? (size_t)(g0 + n)
                              : (size_t)I_DIM + (size_t)g0 + (n - 128);
        gB[j]   = g_ws + wr * H_DIM + kc * 8;
        offB[j] = (uint32_t)(B_OFF + n * 64) + swx;
    }

    auto load_stage = [&](int s, int kt) {
        const uint32_t base = sb + s * STG;
        const int ko = kt * 32;
        cp16(base + offA,          gA + ko);
        cp16(base + A1_OFF + offA, gA + XS_PLANE + ko);
#pragma unroll
        for (int j = 0; j < 4; ++j) {
            cp16(base + offB[j],          gB[j] + ko);
            cp16(base + BP_OFF + offB[j], gB[j] + WS_PLANE + ko);
        }
    };

    // ---- consumer fragment addressing (SW64, 64B rows) ----
    const uint32_t aXor  = (uint32_t)((lane & 6) << 3);
    const uint32_t aCol0 = (uint32_t)((lane >> 4) * 16);
    uint32_t aAddr[2];
#pragma unroll
    for (int ms = 0; ms < 2; ++ms)
        aAddr[ms] = (uint32_t)((wm * 32 + ms * 16 + (lane & 15)) * 64);

    uint32_t bAddr[4];
#pragma unroll
    for (int jj = 0; jj < 4; ++jj) {
        int nloc = wn * 64 + jj * 16 + (lane & 7) + ((lane & 16) >> 1);
        bAddr[jj] = (uint32_t)(nloc * 64);       // (nloc&6)==(lane&6) -> aXor ok
    }
    const uint32_t bCol0 = (uint32_t)(((lane >> 3) & 1) * 16);

    float acc[2][8][4];
#pragma unroll
    for (int ms = 0; ms < 2; ++ms)
#pragma unroll
        for (int j = 0; j < 8; ++j)
#pragma unroll
            for (int e = 0; e < 4; ++e) acc[ms][j][e] = 0.0f;

    load_stage(0, 0); CP_COMMIT();
    load_stage(1, 1); CP_COMMIT();
    load_stage(2, 2); CP_COMMIT();

    const int nK = H_DIM / 32;                   // 128 stages
    for (int kt = 0; kt < nK; ++kt) {
        CP_WAIT2();
        __syncthreads();
        if (kt + 3 < nK) load_stage((kt + 3) & 3, kt + 3);
        CP_COMMIT();

        const uint32_t sbase = sb + (kt & 3) * STG;
#pragma unroll
        for (int t = 0; t < 2; ++t) {
            uint32_t a0[2][4], a1[2][4];
            const uint32_t ac = (t * 32 + aCol0) ^ aXor;
#pragma unroll
            for (int ms = 0; ms < 2; ++ms) {
                ldsm4(a0[ms], sbase + aAddr[ms] + ac);
                ldsm4(a1[ms], sbase + A1_OFF + aAddr[ms] + ac);
            }
#pragma unroll
            for (int jj = 0; jj < 4; ++jj) {
                uint32_t b0[4], b1[4];
                const uint32_t bc = (t * 32 + bCol0) ^ aXor;
                ldsm4(b0, sbase + B_OFF + bAddr[jj] + bc);
                ldsm4(b1, sbase + B_OFF + BP_OFF + bAddr[jj] + bc);
                // term-major: same-accumulator reuse distance = 4
#pragma unroll
                for (int ms = 0; ms < 2; ++ms) {
                    mma16816(acc[ms][jj * 2],     a0[ms], b0[0], b0[1]);
                    mma16816(acc[ms][jj * 2 + 1], a0[ms], b0[2], b0[3]);
                }
#pragma unroll
                for (int ms = 0; ms < 2; ++ms) {
                    mma16816(acc[ms][jj * 2],     a1[ms], b0[0], b0[1]);
                    mma16816(acc[ms][jj * 2 + 1], a1[ms], b0[2], b0[3]);
                }
#pragma unroll
                for (int ms = 0; ms < 2; ++ms) {
                    mma16816(acc[ms][jj * 2],     a0[ms], b1[0], b1[1]);
                    mma16816(acc[ms][jj * 2 + 1], a0[ms], b1[2], b1[3]);
                }
            }
        }
    }

    // ---- epilogue: stash descaled fp32, then silu*mul + fp8 quant ----
    CP_WAIT0();
    __syncthreads();
    float* ys = (float*)smem;                    // 64 x YS floats (~67.5 KB)
    const float inv64 = 0.015625f;
#pragma unroll
    for (int ms = 0; ms < 2; ++ms) {
        const int R = wm * 32 + ms * 16 + (lane >> 2);
#pragma unroll
        for (int j = 0; j < 8; ++j) {
            const int C = wn * 64 + (j >> 1) * 16 + (j & 1) * 8 + (lane & 3) * 2;
            ys[R * YS + C]           = acc[ms][j][0] * inv64;
            ys[R * YS + C + 1]       = acc[ms][j][1] * inv64;
            ys[(R + 8) * YS + C]     = acc[ms][j][2] * inv64;
            ys[(R + 8) * YS + C + 1] = acc[ms][j][3] * inv64;
        }
    }
    __syncthreads();

    float* res = out;
    float* scl = out + (size_t)T_DIM * I_DIM;
#pragma unroll
    for (int rr = 0; rr < 8; ++rr) {
        const int r = wid * 8 + rr;
        const int grow = row0 + r;
        const float* yr = ys + r * YS;
        const int c0 = lane * 4;

        float4 gv = *(const float4*)(yr + c0);
        float4 uv = *(const float4*)(yr + 128 + c0);
        float g4[4] = {gv.x, gv.y, gv.z, gv.w};
        float u4[4] = {uv.x, uv.y, uv.z, uv.w};
        float y[4];
#pragma unroll
        for (int e = 0; e < 4; ++e) {
            float g = g4[e];
            float sg = 1.0f / (1.0f + expf(-g));
            y[e] = g * sg * u4[e];
        }
        float m = fmaxf(fmaxf(fabsf(y[0]), fabsf(y[1])),
                        fmaxf(fabsf(y[2]), fabsf(y[3])));
#pragma unroll
        for (int off = 16; off > 0; off >>= 1)
            m = fmaxf(m, __shfl_xor_sync(0xffffffffu, m, off));
        float amax  = fmaxf(m, 1e-10f);
        float scale = __fdiv_rn(amax, 448.0f);

        float q[4];
#pragma unroll
        for (int e = 0; e < 4; ++e) {
            float qv = __fdiv_rn(y[e], scale);
            qv = fminf(fmaxf(qv, -448.0f), 448.0f);
            __nv_fp8_storage_t b =
                __nv_cvt_float_to_fp8(qv, __NV_SATFINITE, __NV_E4M3);
            __half_raw hr = __nv_cvt_fp8_to_halfraw(b, __NV_E4M3);
            q[e] = __half2float(__half(hr));
        }
        *(float4*)&res[(size_t)grow * I_DIM + g0 + c0] =
            make_float4(q[0], q[1], q[2], q[3]);
        if (lane == 0)
            scl[(size_t)grow * NGROUPS + blockIdx.y] = scale;
    }
}

// ---------------------------------------------------------------- launch
extern "C" void kernel_launch(void* const* d_in, const int* in_sizes, int n_in,
                              void* d_out, int out_size)
{
    const float* x = (const float*)d_in[0];
    const float* W = (const float*)d_in[1];
    float* out = (float*)d_out;

    split_x_kernel<<<4096, 256>>>(x);
    split_w_kernel<<<8192, 256>>>(W);

    cudaFuncSetAttribute(mlp_mma_kernel,
                         cudaFuncAttributeMaxDynamicSharedMemorySize, SMEM_SZ);
    dim3 grid(T_DIM / 64, I_DIM / 128);   // (64, 112)
    mlp_mma_kernel<<<grid, 256, SMEM_SZ>>>(out);
}

// round 10
// speedup vs baseline: 1.1656x; 1.1656x over previous
#include <cuda_runtime.h>
#include <cuda_fp16.h>
#include <cuda_fp8.h>
#include <cstdint>

// Fused gate_up GEMM + SiLU*mul + per-128-group fp8-e4m3 quant via mma.sync
// (HMMA m16n8k16 fp16/fp32-acc). fp16 2-way split, W pre-scaled x64:
// gate_up*64 = x0w0 + x1w0 + x0w1 (dropped x1w1 ~2^-22). Epilogue descales.
//
// R10 = EXACT R5 winner (CTA 64x256, 8 warps 2x4, K=64 2-stage SW128) with
// ONE delta: B-fragment double-buffering (prefetch jj+1's ldsm during jj's
// MMAs). Plus dummy launches to align the main kernel into ncu's -s 5 slot.
//
// Output layout (float32): [T*I fp8-rounded values] ++ [T*(I/128) scales]

#define T_DIM 4096
#define H_DIM 4096
#define I_DIM 14336
#define NGROUPS (I_DIM / 128)

static const size_t XS_PLANE = (size_t)T_DIM * H_DIM;
static const size_t WS_PLANE = (size_t)2 * I_DIM * H_DIM;

__device__ __align__(16) __half g_xs[2ull * 4096ull * 4096ull];   //  64 MB
__device__ __align__(16) __half g_ws[2ull * 28672ull * 4096ull];  // 448 MB
__device__ int g_probe;

// ---------------------------------------------------------------- pre-pass
__global__ __launch_bounds__(256)
void split_x_kernel(const float* __restrict__ src)
{
    const size_t n4 = XS_PLANE / 4;
    size_t i = (size_t)blockIdx.x * blockDim.x + threadIdx.x;
    const size_t stride = (size_t)gridDim.x * blockDim.x;
    for (; i < n4; i += stride) {
        float4 v = ((const float4*)src)[i];
        float f[4] = {v.x, v.y, v.z, v.w};
        __half h0[4], h1[4];
#pragma unroll
        for (int e = 0; e < 4; ++e) {
            h0[e] = __float2half_rn(f[e]);
            h1[e] = __float2half_rn(f[e] - __half2float(h0[e]));
        }
        ((__half2*)(g_xs))[i * 2]                = __halves2half2(h0[0], h0[1]);
        ((__half2*)(g_xs))[i * 2 + 1]            = __halves2half2(h0[2], h0[3]);
        ((__half2*)(g_xs + XS_PLANE))[i * 2]     = __halves2half2(h1[0], h1[1]);
        ((__half2*)(g_xs + XS_PLANE))[i * 2 + 1] = __halves2half2(h1[2], h1[3]);
    }
}

__global__ __launch_bounds__(256)
void split_w_kernel(const float* __restrict__ src)
{
    const size_t n4 = WS_PLANE / 4;
    size_t i = (size_t)blockIdx.x * blockDim.x + threadIdx.x;
    const size_t stride = (size_t)gridDim.x * blockDim.x;
    for (; i < n4; i += stride) {
        float4 v = ((const float4*)src)[i];
        float f[4] = {v.x * 64.0f, v.y * 64.0f, v.z * 64.0f, v.w * 64.0f};
        __half h0[4], h1[4];
#pragma unroll
        for (int e = 0; e < 4; ++e) {
            h0[e] = __float2half_rn(f[e]);
            h1[e] = __float2half_rn(f[e] - __half2float(h0[e]));
        }
        ((__half2*)(g_ws))[i * 2]                = __halves2half2(h0[0], h0[1]);
        ((__half2*)(g_ws))[i * 2 + 1]            = __halves2half2(h0[2], h0[3]);
        ((__half2*)(g_ws + WS_PLANE))[i * 2]     = __halves2half2(h1[0], h1[1]);
        ((__half2*)(g_ws + WS_PLANE))[i * 2 + 1] = __halves2half2(h1[2], h1[3]);
    }
}

// Tiny alignment kernel so the main GEMM lands in ncu's -s 5 capture slot.
__global__ void probe_kernel()
{
    if (threadIdx.x == 0 && blockIdx.x == 0) g_probe = 1;
}

// ---------------------------------------------------------------- main GEMM
// CTA tile: M=64 x N=256 (128 gate + 128 up W rows). 8 warps in a 2x4
// grid -> warp tile 32x64. K staged 64 elems/stage, 2 cp.async stages.
// SMEM per stage: A0|A1 (64x128B each = 8KB) + B0|B1 (256x128B = 32KB each).

#define STG      81920                 // bytes per stage
#define A1_OFF   8192
#define B0_OFF   16384
#define B1_OFF   49152
#define SMEM_SZ  (2 * STG)             // 160 KB
#define YS       264                   // f32 stride of epilogue stash

__device__ __forceinline__ uint32_t s2u(const void* p) {
    uint32_t a;
    asm("{ .reg .u64 t; cvta.to.shared.u64 t, %1; cvt.u32.u64 %0, t; }"
        : "=r"(a) : "l"(p));
    return a;
}
__device__ __forceinline__ void cp16(uint32_t s, const void* g) {
    asm volatile("cp.async.cg.shared.global [%0], [%1], 16;"
                 :: "r"(s), "l"(g) : "memory");
}
#define CP_COMMIT() asm volatile("cp.async.commit_group;" ::: "memory")
#define CP_WAIT1()  asm volatile("cp.async.wait_group 1;" ::: "memory")

__device__ __forceinline__ void ldsm4(uint32_t* r, uint32_t addr) {
    asm volatile("ldmatrix.sync.aligned.m8n8.x4.shared.b16 {%0,%1,%2,%3}, [%4];"
                 : "=r"(r[0]), "=r"(r[1]), "=r"(r[2]), "=r"(r[3]) : "r"(addr));
}
__device__ __forceinline__ void mma16816(float* c, const uint32_t* a,
                                         uint32_t b0, uint32_t b1) {
    asm volatile(
        "mma.sync.aligned.m16n8k16.row.col.f32.f16.f16.f32 "
        "{%0,%1,%2,%3}, {%4,%5,%6,%7}, {%8,%9}, {%0,%1,%2,%3};"
        : "+f"(c[0]), "+f"(c[1]), "+f"(c[2]), "+f"(c[3])
        : "r"(a[0]), "r"(a[1]), "r"(a[2]), "r"(a[3]), "r"(b0), "r"(b1));
}

__global__ __launch_bounds__(256)
void mlp_mma_kernel(float* __restrict__ out)
{
    extern __shared__ __align__(1024) char smem[];
    const uint32_t sb = s2u(smem);
    const int tid = threadIdx.x;
    const int lane = tid & 31, wid = tid >> 5;
    const int wm = wid >> 2, wn = wid & 3;
    const int row0 = blockIdx.x * 64;
    const int g0   = blockIdx.y * 128;

    // ---- producer addressing: thread owns (row r0a, 16B chunk kc) ----
    const int kc = tid & 7;          // k-chunk within 128B row
    const int r0a = tid >> 3;        // 0..31
    uint32_t sw0 = (uint32_t)(r0a * 128 + kc * 16);
    sw0 ^= (sw0 >> 3) & 0x70;        // SW128

    const __half* gx0 = &g_xs[(size_t)(row0 + r0a) * H_DIM + kc * 8];
    const __half* gw0[8];
#pragma unroll
    for (int k = 0; k < 8; ++k) {
        int n = r0a + 32 * k;        // 0..255 local B row
        size_t wr = (n < 128) ? (size_t)(g0 + n)
                              : (size_t)I_DIM + (size_t)g0 + (n - 128);
        gw0[k] = &g_ws[wr * H_DIM + kc * 8];
    }

    auto load_stage = [&](int s, int kt) {
        const uint32_t base = sb + s * STG + sw0;
        const __half* x0 = gx0 + kt * 64;
        cp16(base,                    x0);
        cp16(base + 4096,             x0 + 32 * H_DIM);
        cp16(base + A1_OFF,           x0 + XS_PLANE);
        cp16(base + A1_OFF + 4096,    x0 + XS_PLANE + 32 * H_DIM);
#pragma unroll
        for (int k = 0; k < 8; ++k) {
            const __half* w0 = gw0[k] + kt * 64;
            cp16(base + B0_OFF + k * 4096, w0);
            cp16(base + B1_OFF + k * 4096, w0 + WS_PLANE);
        }
    };

    // ---- consumer fragment addressing ----
    const uint32_t xorv = (uint32_t)((lane & 7) << 4);
    const uint32_t aRow = (uint32_t)((wm * 32 + (lane & 15)) * 128);
    const uint32_t aChk = (uint32_t)((lane >> 4) * 16);
    const int nloc = wn * 64 + (lane & 7) + ((lane & 16) >> 1);
    const uint32_t bRow = (uint32_t)(nloc * 128);
    const uint32_t bChk = (uint32_t)(((lane >> 3) & 1) * 16);

    float acc[2][8][4];
#pragma unroll
    for (int i = 0; i < 2; ++i)
#pragma unroll
        for (int j = 0; j < 8; ++j)
#pragma unroll
            for (int e = 0; e < 4; ++e) acc[i][j][e] = 0.0f;

    load_stage(0, 0); CP_COMMIT();
    load_stage(1, 1); CP_COMMIT();

    const int nK = H_DIM / 64;       // 64 stages
    for (int kt = 0; kt < nK; ++kt) {
        const int s = kt & 1;
        CP_WAIT1();
        __syncthreads();
        const uint32_t sbase = sb + s * STG;

#pragma unroll
        for (int t = 0; t < 4; ++t) {
            uint32_t a[2][2][4];
#pragma unroll
            for (int p = 0; p < 2; ++p)
#pragma unroll
                for (int i = 0; i < 2; ++i)
                    ldsm4(a[p][i], sbase + p * A1_OFF + aRow + i * 2048 +
                                   ((t * 32 + aChk) ^ xorv));

            // B double-buffer: prefetch jj+1 fragments during jj's MMAs
            uint32_t b0[2][4], b1[2][4];
            {
                const uint32_t bc = ((t * 32 + bChk) ^ xorv) + bRow;
                ldsm4(b0[0], sbase + B0_OFF + bc);
                ldsm4(b1[0], sbase + B1_OFF + bc);
            }
#pragma unroll
            for (int jj = 0; jj < 4; ++jj) {
                const int cur = jj & 1, nxt = cur ^ 1;
                if (jj < 3) {
                    const uint32_t bc = ((t * 32 + bChk) ^ xorv)
                                      + (jj + 1) * 2048 + bRow;
                    ldsm4(b0[nxt], sbase + B0_OFF + bc);
                    ldsm4(b1[nxt], sbase + B1_OFF + bc);
                }
#pragma unroll
                for (int i = 0; i < 2; ++i) {
#pragma unroll
                    for (int h = 0; h < 2; ++h) {
                        float* c = acc[i][jj * 2 + h];
                        mma16816(c, a[0][i], b0[cur][2 * h], b0[cur][2 * h + 1]);
                        mma16816(c, a[1][i], b0[cur][2 * h], b0[cur][2 * h + 1]);
                        mma16816(c, a[0][i], b1[cur][2 * h], b1[cur][2 * h + 1]);
                    }
                }
            }
        }
        __syncthreads();
        if (kt + 2 < nK) load_stage(s, kt + 2);
        CP_COMMIT();
    }

    // ---- epilogue: stash descaled fp32 tile, then silu*mul + fp8 quant ----
    float* ys = (float*)smem;        // 64 x YS floats (stage buffers dead)
    const float inv64 = 0.015625f;
#pragma unroll
    for (int i = 0; i < 2; ++i) {
#pragma unroll
        for (int j = 0; j < 8; ++j) {
            const int R = wm * 32 + i * 16 + (lane >> 2);
            const int C = wn * 64 + j * 8 + (lane & 3) * 2;
            ys[R * YS + C]           = acc[i][j][0] * inv64;
            ys[R * YS + C + 1]       = acc[i][j][1] * inv64;
            ys[(R + 8) * YS + C]     = acc[i][j][2] * inv64;
            ys[(R + 8) * YS + C + 1] = acc[i][j][3] * inv64;
        }
    }
    __syncthreads();

    float* res = out;
    float* scl = out + (size_t)T_DIM * I_DIM;
#pragma unroll
    for (int rr = 0; rr < 8; ++rr) {
        const int r = wid * 8 + rr;
        const int grow = row0 + r;
        const float* yr = ys + r * YS;
        const int c0 = lane * 4;

        float4 gv = *(const float4*)(yr + c0);
        float4 uv = *(const float4*)(yr + 128 + c0);
        float g4[4] = {gv.x, gv.y, gv.z, gv.w};
        float u4[4] = {uv.x, uv.y, uv.z, uv.w};
        float y[4];
#pragma unroll
        for (int e = 0; e < 4; ++e) {
            float g = g4[e];
            float sg = 1.0f / (1.0f + expf(-g));
            y[e] = g * sg * u4[e];
        }
        float m = fmaxf(fmaxf(fabsf(y[0]), fabsf(y[1])),
                        fmaxf(fabsf(y[2]), fabsf(y[3])));
#pragma unroll
        for (int off = 16; off > 0; off >>= 1)
            m = fmaxf(m, __shfl_xor_sync(0xffffffffu, m, off));
        float amax  = fmaxf(m, 1e-10f);
        float scale = __fdiv_rn(amax, 448.0f);

        float q[4];
#pragma unroll
        for (int e = 0; e < 4; ++e) {
            float qv = __fdiv_rn(y[e], scale);
            qv = fminf(fmaxf(qv, -448.0f), 448.0f);
            __nv_fp8_storage_t b =
                __nv_cvt_float_to_fp8(qv, __NV_SATFINITE, __NV_E4M3);
            __half_raw hr = __nv_cvt_fp8_to_halfraw(b, __NV_E4M3);
            q[e] = __half2float(__half(hr));
        }
        *(float4*)&res[(size_t)grow * I_DIM + g0 + c0] =
            make_float4(q[0], q[1], q[2], q[3]);
        if (lane == 0)
            scl[(size_t)grow * NGROUPS + blockIdx.y] = scale;
    }
}

// ---------------------------------------------------------------- launch
extern "C" void kernel_launch(void* const* d_in, const int* in_sizes, int n_in,
                              void* d_out, int out_size)
{
    const float* x = (const float*)d_in[0];
    const float* W = (const float*)d_in[1];
    float* out = (float*)d_out;

    cudaFuncSetAttribute(mlp_mma_kernel,
                         cudaFuncAttributeMaxDynamicSharedMemorySize, SMEM_SZ);

    // Period-6 launch pattern so the GEMM lands in ncu's "-s 5" capture slot
    // (observed aliasing: launch 5 == position 0 with the old period-3 order).
    split_x_kernel<<<4096, 256>>>(x);                        // pos 0
    split_w_kernel<<<8192, 256>>>(W);                        // pos 1
    probe_kernel<<<1, 32>>>();                               // pos 2
    dim3 grid(T_DIM / 64, I_DIM / 128);                      // (64, 112)
    mlp_mma_kernel<<<grid, 256, SMEM_SZ>>>(out);             // pos 3
    probe_kernel<<<1, 32>>>();                               // pos 4
    probe_kernel<<<1, 32>>>();                               // pos 5
}

// round 11
// speedup vs baseline: 1.1914x; 1.0221x over previous
#include <cuda_runtime.h>
#include <cuda_fp16.h>
#include <cuda_fp8.h>
#include <cstdint>

// Fused gate_up GEMM + SiLU*mul + per-128-group fp8-e4m3 quant via mma.sync
// (HMMA m16n8k16 fp16/fp32-acc). fp16 2-way split, W pre-scaled x64:
// gate_up*64 = x0w0 + x1w0 + x0w1 (dropped x1w1 ~2^-22). Epilogue descales.
//
// R11: same winning tile (CTA 64x256, 8 warps 2x4, warp 32x64) but stage
// shrunk to K=32 (40KB, SW64) x 2 stages = 80KB and regs capped so TWO CTAs
// co-reside per SM (occ 12.5%->25%) to fill the 25% tensor-pipe bubble the
// R10 profile exposed (tensor=74.8%, all memory pipes far from caps).
//
// Output layout (float32): [T*I fp8-rounded values] ++ [T*(I/128) scales]

#define T_DIM 4096
#define H_DIM 4096
#define I_DIM 14336
#define NGROUPS (I_DIM / 128)

static const size_t XS_PLANE = (size_t)T_DIM * H_DIM;
static const size_t WS_PLANE = (size_t)2 * I_DIM * H_DIM;

__device__ __align__(16) __half g_xs[2ull * 4096ull * 4096ull];   //  64 MB
__device__ __align__(16) __half g_ws[2ull * 28672ull * 4096ull];  // 448 MB
__device__ int g_probe;

// ---------------------------------------------------------------- pre-pass
__global__ __launch_bounds__(256)
void split_x_kernel(const float* __restrict__ src)
{
    const size_t n4 = XS_PLANE / 4;
    size_t i = (size_t)blockIdx.x * blockDim.x + threadIdx.x;
    const size_t stride = (size_t)gridDim.x * blockDim.x;
    for (; i < n4; i += stride) {
        float4 v = ((const float4*)src)[i];
        float f[4] = {v.x, v.y, v.z, v.w};
        __half h0[4], h1[4];
#pragma unroll
        for (int e = 0; e < 4; ++e) {
            h0[e] = __float2half_rn(f[e]);
            h1[e] = __float2half_rn(f[e] - __half2float(h0[e]));
        }
        ((__half2*)(g_xs))[i * 2]                = __halves2half2(h0[0], h0[1]);
        ((__half2*)(g_xs))[i * 2 + 1]            = __halves2half2(h0[2], h0[3]);
        ((__half2*)(g_xs + XS_PLANE))[i * 2]     = __halves2half2(h1[0], h1[1]);
        ((__half2*)(g_xs + XS_PLANE))[i * 2 + 1] = __halves2half2(h1[2], h1[3]);
    }
}

__global__ __launch_bounds__(256)
void split_w_kernel(const float* __restrict__ src)
{
    const size_t n4 = WS_PLANE / 4;
    size_t i = (size_t)blockIdx.x * blockDim.x + threadIdx.x;
    const size_t stride = (size_t)gridDim.x * blockDim.x;
    for (; i < n4; i += stride) {
        float4 v = ((const float4*)src)[i];
        float f[4] = {v.x * 64.0f, v.y * 64.0f, v.z * 64.0f, v.w * 64.0f};
        __half h0[4], h1[4];
#pragma unroll
        for (int e = 0; e < 4; ++e) {
            h0[e] = __float2half_rn(f[e]);
            h1[e] = __float2half_rn(f[e] - __half2float(h0[e]));
        }
        ((__half2*)(g_ws))[i * 2]                = __halves2half2(h0[0], h0[1]);
        ((__half2*)(g_ws))[i * 2 + 1]            = __halves2half2(h0[2], h0[3]);
        ((__half2*)(g_ws + WS_PLANE))[i * 2]     = __halves2half2(h1[0], h1[1]);
        ((__half2*)(g_ws + WS_PLANE))[i * 2 + 1] = __halves2half2(h1[2], h1[3]);
    }
}

// Tiny alignment kernel so the main GEMM lands in ncu's -s 5 capture slot.
__global__ void probe_kernel()
{
    if (threadIdx.x == 0 && blockIdx.x == 0) g_probe = 1;
}

// ---------------------------------------------------------------- main GEMM
// Stage (K=32): A0|A1 (64x64B = 4KB each) + B0|B1 (256x64B = 16KB each).
#define STG      40960
#define A1_OFF   4096
#define B_OFF    8192
#define BP_OFF   16384                // B1 = B_OFF + BP_OFF
#define SMEM_SZ  (2 * STG)            // 80 KB -> 2 CTAs/SM
#define YS       264

__device__ __forceinline__ uint32_t s2u(const void* p) {
    uint32_t a;
    asm("{ .reg .u64 t; cvta.to.shared.u64 t, %1; cvt.u32.u64 %0, t; }"
        : "=r"(a) : "l"(p));
    return a;
}
__device__ __forceinline__ void cp16(uint32_t s, const void* g) {
    asm volatile("cp.async.cg.shared.global [%0], [%1], 16;"
                 :: "r"(s), "l"(g) : "memory");
}
#define CP_COMMIT() asm volatile("cp.async.commit_group;" ::: "memory")
#define CP_WAIT1()  asm volatile("cp.async.wait_group 1;" ::: "memory")

__device__ __forceinline__ void ldsm4(uint32_t* r, uint32_t addr) {
    asm volatile("ldmatrix.sync.aligned.m8n8.x4.shared.b16 {%0,%1,%2,%3}, [%4];"
                 : "=r"(r[0]), "=r"(r[1]), "=r"(r[2]), "=r"(r[3]) : "r"(addr));
}
__device__ __forceinline__ void mma16816(float* c, const uint32_t* a,
                                         uint32_t b0, uint32_t b1) {
    asm volatile(
        "mma.sync.aligned.m16n8k16.row.col.f32.f16.f16.f32 "
        "{%0,%1,%2,%3}, {%4,%5,%6,%7}, {%8,%9}, {%0,%1,%2,%3};"
        : "+f"(c[0]), "+f"(c[1]), "+f"(c[2]), "+f"(c[3])
        : "r"(a[0]), "r"(a[1]), "r"(a[2]), "r"(a[3]), "r"(b0), "r"(b1));
}

__global__ __launch_bounds__(256, 2)
void mlp_mma_kernel(float* __restrict__ out)
{
    extern __shared__ __align__(1024) char smem[];
    const uint32_t sb = s2u(smem);
    const int tid = threadIdx.x;
    const int lane = tid & 31, wid = tid >> 5;
    const int wm = wid >> 2, wn = wid & 3;       // 2x4 warp grid
    const int row0 = blockIdx.x * 64;
    const int g0   = blockIdx.y * 128;

    // ---- producer: 10 x 16B chunks per thread per stage (SW64 rows) ----
    const int kc    = tid & 3;                   // 16B chunk within 64B row
    const int rowid = tid >> 2;                  // 0..63
    const uint32_t swx = (uint32_t)((kc * 16) ^ ((rowid & 6) << 3));

    const __half* gA = g_xs + (size_t)(row0 + rowid) * H_DIM + kc * 8;
    const uint32_t offA = (uint32_t)(rowid * 64) + swx;

    const __half* gB[4];
    uint32_t offB[4];
#pragma unroll
    for (int j = 0; j < 4; ++j) {
        int n = rowid + 64 * j;                  // 0..255
        size_t wr = (n < 128) ? (size_t)(g0 + n)
                              : (size_t)I_DIM + (size_t)g0 + (n - 128);
        gB[j]   = g_ws + wr * H_DIM + kc * 8;
        offB[j] = (uint32_t)(B_OFF + n * 64) + swx;
    }

    auto load_stage = [&](int s, int kt) {
        const uint32_t base = sb + s * STG;
        const int ko = kt * 32;
        cp16(base + offA,          gA + ko);
        cp16(base + A1_OFF + offA, gA + XS_PLANE + ko);
#pragma unroll
        for (int j = 0; j < 4; ++j) {
            cp16(base + offB[j],          gB[j] + ko);
            cp16(base + BP_OFF + offB[j], gB[j] + WS_PLANE + ko);
        }
    };

    // ---- consumer fragment addressing (SW64, 64B rows; verified in R8) ----
    const uint32_t aXor  = (uint32_t)((lane & 6) << 3);
    const uint32_t aCol0 = (uint32_t)((lane >> 4) * 16);
    uint32_t aAddr[2];
#pragma unroll
    for (int ms = 0; ms < 2; ++ms)
        aAddr[ms] = (uint32_t)((wm * 32 + ms * 16 + (lane & 15)) * 64);

    uint32_t bAddr[4];
#pragma unroll
    for (int jj = 0; jj < 4; ++jj) {
        int nloc = wn * 64 + jj * 16 + (lane & 7) + ((lane & 16) >> 1);
        bAddr[jj] = (uint32_t)(nloc * 64);       // (nloc&6)==(lane&6)
    }
    const uint32_t bCol0 = (uint32_t)(((lane >> 3) & 1) * 16);

    float acc[2][8][4];
#pragma unroll
    for (int ms = 0; ms < 2; ++ms)
#pragma unroll
        for (int j = 0; j < 8; ++j)
#pragma unroll
            for (int e = 0; e < 4; ++e) acc[ms][j][e] = 0.0f;

    load_stage(0, 0); CP_COMMIT();
    load_stage(1, 1); CP_COMMIT();

    const int nK = H_DIM / 32;                   // 128 stages
    for (int kt = 0; kt < nK; ++kt) {
        const int s = kt & 1;
        CP_WAIT1();
        __syncthreads();
        const uint32_t sbase = sb + s * STG;

#pragma unroll
        for (int t = 0; t < 2; ++t) {
            uint32_t a0[2][4], a1[2][4];
            const uint32_t ac = (t * 32 + aCol0) ^ aXor;
#pragma unroll
            for (int ms = 0; ms < 2; ++ms) {
                ldsm4(a0[ms], sbase + aAddr[ms] + ac);
                ldsm4(a1[ms], sbase + A1_OFF + aAddr[ms] + ac);
            }
#pragma unroll
            for (int jj = 0; jj < 4; ++jj) {
                uint32_t b0[4], b1[4];
                const uint32_t bc = (t * 32 + bCol0) ^ aXor;
                ldsm4(b0, sbase + B_OFF + bAddr[jj] + bc);
                ldsm4(b1, sbase + B_OFF + BP_OFF + bAddr[jj] + bc);
#pragma unroll
                for (int ms = 0; ms < 2; ++ms) {
#pragma unroll
                    for (int h = 0; h < 2; ++h) {
                        float* c = acc[ms][jj * 2 + h];
                        mma16816(c, a0[ms], b0[2 * h], b0[2 * h + 1]); // x0*w0
                        mma16816(c, a1[ms], b0[2 * h], b0[2 * h + 1]); // x1*w0
                        mma16816(c, a0[ms], b1[2 * h], b1[2 * h + 1]); // x0*w1
                    }
                }
            }
        }
        __syncthreads();
        if (kt + 2 < nK) load_stage(s, kt + 2);
        CP_COMMIT();
    }

    // ---- epilogue: stash descaled fp32, then silu*mul + fp8 quant ----
    __syncthreads();
    float* ys = (float*)smem;                    // 64 x YS floats (~67.5 KB)
    const float inv64 = 0.015625f;
#pragma unroll
    for (int ms = 0; ms < 2; ++ms) {
#pragma unroll
        for (int j = 0; j < 8; ++j) {
            const int R = wm * 32 + ms * 16 + (lane >> 2);
            const int C = wn * 64 + j * 8 + (lane & 3) * 2;
            ys[R * YS + C]           = acc[ms][j][0] * inv64;
            ys[R * YS + C + 1]       = acc[ms][j][1] * inv64;
            ys[(R + 8) * YS + C]     = acc[ms][j][2] * inv64;
            ys[(R + 8) * YS + C + 1] = acc[ms][j][3] * inv64;
        }
    }
    __syncthreads();

    float* res = out;
    float* scl = out + (size_t)T_DIM * I_DIM;
#pragma unroll
    for (int rr = 0; rr < 8; ++rr) {
        const int r = wid * 8 + rr;
        const int grow = row0 + r;
        const float* yr = ys + r * YS;
        const int c0 = lane * 4;

        float4 gv = *(const float4*)(yr + c0);
        float4 uv = *(const float4*)(yr + 128 + c0);
        float g4[4] = {gv.x, gv.y, gv.z, gv.w};
        float u4[4] = {uv.x, uv.y, uv.z, uv.w};
        float y[4];
#pragma unroll
        for (int e = 0; e < 4; ++e) {
            float g = g4[e];
            float sg = 1.0f / (1.0f + expf(-g));
            y[e] = g * sg * u4[e];
        }
        float m = fmaxf(fmaxf(fabsf(y[0]), fabsf(y[1])),
                        fmaxf(fabsf(y[2]), fabsf(y[3])));
#pragma unroll
        for (int off = 16; off > 0; off >>= 1)
            m = fmaxf(m, __shfl_xor_sync(0xffffffffu, m, off));
        float amax  = fmaxf(m, 1e-10f);
        float scale = __fdiv_rn(amax, 448.0f);

        float q[4];
#pragma unroll
        for (int e = 0; e < 4; ++e) {
            float qv = __fdiv_rn(y[e], scale);
            qv = fminf(fmaxf(qv, -448.0f), 448.0f);
            __nv_fp8_storage_t b =
                __nv_cvt_float_to_fp8(qv, __NV_SATFINITE, __NV_E4M3);
            __half_raw hr = __nv_cvt_fp8_to_halfraw(b, __NV_E4M3);
            q[e] = __half2float(__half(hr));
        }
        *(float4*)&res[(size_t)grow * I_DIM + g0 + c0] =
            make_float4(q[0], q[1], q[2], q[3]);
        if (lane == 0)
            scl[(size_t)grow * NGROUPS + blockIdx.y] = scale;
    }
}

// ---------------------------------------------------------------- launch
extern "C" void kernel_launch(void* const* d_in, const int* in_sizes, int n_in,
                              void* d_out, int out_size)
{
    const float* x = (const float*)d_in[0];
    const float* W = (const float*)d_in[1];
    float* out = (float*)d_out;

    cudaFuncSetAttribute(mlp_mma_kernel,
                         cudaFuncAttributeMaxDynamicSharedMemorySize, SMEM_SZ);

    // Period-6 launch pattern keeps the GEMM in ncu's "-s 5" capture slot.
    split_x_kernel<<<4096, 256>>>(x);                        // pos 0
    split_w_kernel<<<8192, 256>>>(W);                        // pos 1
    probe_kernel<<<1, 32>>>();                               // pos 2
    dim3 grid(T_DIM / 64, I_DIM / 128);                      // (64, 112)
    mlp_mma_kernel<<<grid, 256, SMEM_SZ>>>(out);             // pos 3
    probe_kernel<<<1, 32>>>();                               // pos 4
    probe_kernel<<<1, 32>>>();                               // pos 5
}